// round 1
// baseline (speedup 1.0000x reference)
#include <cuda_runtime.h>

#define BATCH 32
#define NATOM 128
#define HH 64
#define WW 64
#define OH 57
#define SPP (OH*OH)           // 3249
#define NPS (NATOM*SPP)       // 415872
#define KSEL 256
#define NAL 17
#define CAP 2048
#define NBINS 4096
#define IMGPIX (HH*WW)        // 4096

// ---------------- device state ----------------
__device__ float d_R[BATCH*IMGPIX];
__device__ float d_g[BATCH*NPS];              // ~53 MB
__device__ int   d_hist[BATCH*NBINS];
__device__ int   d_thr[BATCH];
__device__ int   d_ccnt[BATCH];
__device__ int   d_cpos[BATCH*CAP];
__device__ float d_cg[BATCH*CAP];
__device__ int   d_selp[NAL*BATCH*KSEL];
__device__ float d_selv[NAL*BATCH*KSEL];
__device__ float d_errp[NAL*BATCH];
__device__ float d_l2p[BATCH];
__device__ int   d_chosen;
__device__ int   d_supp[BATCH*KSEL];
__device__ int   d_nsup[BATCH];

// ---------------- kernels ----------------

__global__ void k_init(float* __restrict__ X) {
    int stride = gridDim.x * blockDim.x;
    for (int i = blockIdx.x * blockDim.x + threadIdx.x; i < BATCH*NPS; i += stride)
        X[i] = 0.f;
    if (blockIdx.x == 0 && threadIdx.x < BATCH) d_nsup[threadIdx.x] = 0;
}

__global__ void k_iter_init() {
    int gid = blockIdx.x * blockDim.x + threadIdx.x;   // 512*256 = 131072 = BATCH*NBINS
    d_hist[gid] = 0;
    if (gid < BATCH) { d_ccnt[gid] = 0; d_l2p[gid] = 0.f; }
    if (gid < NAL*BATCH) d_errp[gid] = 0.f;
}

// residual R = Y - conv_D(X_sparse);  per-sample l2
__global__ void k_residual(const float* __restrict__ Y, const float* __restrict__ Wg,
                           const float* __restrict__ X) {
    __shared__ float syh[IMGPIX];
    __shared__ float sred[8];
    int s = blockIdx.x, tid = threadIdx.x;
    for (int i = tid; i < IMGPIX; i += 256) syh[i] = 0.f;
    __syncthreads();
    int ns = d_nsup[s];
    if (tid < ns) {
        int pos = d_supp[s*KSEL + tid];
        if (pos >= 0) {
            float val = X[s*NPS + pos];
            int a = pos / SPP, rem = pos - a*SPP, u = rem / OH, v = rem - u*OH;
            const float* w = Wg + a*64;
            #pragma unroll
            for (int p = 0; p < 8; p++)
                #pragma unroll
                for (int q = 0; q < 8; q++)
                    atomicAdd(&syh[(u+p)*WW + v + q], val * w[p*8 + q]);
        }
    }
    __syncthreads();
    float e = 0.f;
    for (int i = tid; i < IMGPIX; i += 256) {
        float r = Y[s*IMGPIX + i] - syh[i];
        d_R[s*IMGPIX + i] = r;
        e += r*r;
    }
    for (int o = 16; o; o >>= 1) e += __shfl_down_sync(0xffffffffu, e, o);
    if ((tid & 31) == 0) sred[tid >> 5] = e;
    __syncthreads();
    if (tid < 32) {
        e = (tid < 8) ? sred[tid] : 0.f;
        for (int o = 4; o; o >>= 1) e += __shfl_down_sync(0xffffffffu, e, o);
        if (tid == 0) d_l2p[s] = e;
    }
}

// g[b,a,u,v] = sum_{p,q} R[b,u+p,v+q] * W[a, q, p]   (Wt = swapaxes(W,2,3))
__global__ void __launch_bounds__(256) k_conv_g(const float* __restrict__ Wg) {
    __shared__ float shR[IMGPIX];
    __shared__ float shW[16*64];
    int s = blockIdx.x >> 3, grp = blockIdx.x & 7, abase = grp * 16;
    int tid = threadIdx.x;
    for (int i = tid; i < IMGPIX; i += 256) shR[i] = d_R[s*IMGPIX + i];
    for (int i = tid; i < 1024; i += 256) {
        int al = i >> 6, pq = i & 63, p = pq >> 3, q = pq & 7;
        shW[i] = Wg[(abase + al)*64 + q*8 + p];   // bake in transpose
    }
    __syncthreads();
    int v = tid & 63, ty = tid >> 6;
    if (v >= OH) return;
    for (int ub = 0; ub < OH; ub += 16) {
        int u0 = ub + ty*4;
        float acc[16][4];
        #pragma unroll
        for (int a = 0; a < 16; a++)
            #pragma unroll
            for (int uu = 0; uu < 4; uu++) acc[a][uu] = 0.f;
        #pragma unroll 1
        for (int p = 0; p < 8; p++) {
            #pragma unroll
            for (int q = 0; q < 8; q++) {
                float w[16];
                #pragma unroll
                for (int a = 0; a < 16; a++) w[a] = shW[a*64 + p*8 + q];
                float r[4];
                #pragma unroll
                for (int uu = 0; uu < 4; uu++) {
                    int u = u0 + uu;
                    r[uu] = (u < OH) ? shR[(u+p)*WW + v + q] : 0.f;
                }
                #pragma unroll
                for (int a = 0; a < 16; a++)
                    #pragma unroll
                    for (int uu = 0; uu < 4; uu++)
                        acc[a][uu] += w[a] * r[uu];
            }
        }
        #pragma unroll
        for (int uu = 0; uu < 4; uu++) {
            int u = u0 + uu;
            if (u < OH) {
                int base = s*NPS + abase*SPP + u*OH + v;
                #pragma unroll
                for (int a = 0; a < 16; a++)
                    d_g[base + a*SPP] = acc[a][uu];
            }
        }
    }
}

__global__ void k_hist() {
    __shared__ int sh[NBINS];
    int s = blockIdx.y, chunk = blockIdx.x;
    for (int i = threadIdx.x; i < NBINS; i += 256) sh[i] = 0;
    __syncthreads();
    int base = chunk * 8192;
    int end = base + 8192; if (end > NPS) end = NPS;
    for (int i = base + threadIdx.x; i < end; i += 256) {
        unsigned ab = __float_as_uint(d_g[s*NPS + i]) & 0x7fffffffu;
        atomicAdd(&sh[ab >> 19], 1);
    }
    __syncthreads();
    for (int i = threadIdx.x; i < NBINS; i += 256)
        if (sh[i]) atomicAdd(&d_hist[s*NBINS + i], sh[i]);
}

__global__ void k_thresh() {
    __shared__ int seg[256];
    int s = blockIdx.x, t = threadIdx.x;
    int sum = 0;
    for (int b = t*16; b < t*16 + 16; b++) sum += d_hist[s*NBINS + b];
    seg[t] = sum;
    __syncthreads();
    if (t == 0) {
        int cum = 0, thr = 0;
        for (int j = 255; j >= 0; j--) {
            if (cum + seg[j] >= 2*KSEL) {
                for (int b = j*16 + 15; b >= j*16; b--) {
                    cum += d_hist[s*NBINS + b];
                    if (cum >= 2*KSEL) { thr = b; break; }
                }
                break;
            }
            cum += seg[j];
        }
        d_thr[s] = thr;
    }
}

__global__ void k_collect() {
    int s = blockIdx.y, chunk = blockIdx.x;
    int thr = d_thr[s];
    int base = chunk * 8192;
    int end = base + 8192; if (end > NPS) end = NPS;
    for (int i = base + threadIdx.x; i < end; i += 256) {
        float gv = d_g[s*NPS + i];
        int key = (int)((__float_as_uint(gv) & 0x7fffffffu) >> 19);
        if (key >= thr) {
            int idx = atomicAdd(&d_ccnt[s], 1);
            if (idx < CAP) { d_cpos[s*CAP + idx] = i; d_cg[s*CAP + idx] = gv; }
        }
    }
}

// append support positions whose |g| fell below threshold (not captured by k_collect)
__global__ void k_suppl() {
    int s = blockIdx.x, tid = threadIdx.x;
    int ns = d_nsup[s];
    if (tid < ns) {
        int pos = d_supp[s*KSEL + tid];
        if (pos >= 0) {
            float gv = d_g[s*NPS + pos];
            int key = (int)((__float_as_uint(gv) & 0x7fffffffu) >> 19);
            if (key < d_thr[s]) {
                int idx = atomicAdd(&d_ccnt[s], 1);
                if (idx < CAP) { d_cpos[s*CAP + idx] = pos; d_cg[s*CAP + idx] = gv; }
            }
        }
    }
}

// one block per (alpha, sample): exact top-256 of |X + a*g| among candidates, then err
__global__ void __launch_bounds__(512) k_attempt(const float* __restrict__ Y,
                                                 const float* __restrict__ Wg,
                                                 const float* __restrict__ X) {
    __shared__ unsigned long long sk[CAP];
    __shared__ float syh[IMGPIX];
    __shared__ float sred[16];
    int ka = blockIdx.x, s = blockIdx.y, tid = threadIdx.x;
    float alpha = 1.0f / (float)(1 << ka);
    int n = d_ccnt[s]; if (n > CAP) n = CAP;
    for (int i = tid; i < CAP; i += 512) {
        unsigned long long kk = 0ull;
        if (i < n) {
            int pos = d_cpos[s*CAP + i];
            float val = X[s*NPS + pos] + alpha * d_cg[s*CAP + i];
            unsigned ab = __float_as_uint(val) & 0x7fffffffu;
            kk = ((unsigned long long)ab << 19) | (unsigned)((~pos) & 0x7ffff);
        }
        sk[i] = kk;
    }
    // bitonic sort, descending (ties: abs desc, then index asc via ~pos)
    for (int k2 = 2; k2 <= CAP; k2 <<= 1)
        for (int j = k2 >> 1; j > 0; j >>= 1) {
            __syncthreads();
            for (int i = tid; i < CAP; i += 512) {
                int ixj = i ^ j;
                if (ixj > i) {
                    unsigned long long a = sk[i], b = sk[ixj];
                    bool sw = ((i & k2) == 0) ? (a < b) : (a > b);
                    if (sw) { sk[i] = b; sk[ixj] = a; }
                }
            }
        }
    __syncthreads();
    int mypos = -1; float myval = 0.f;
    if (tid < KSEL) {
        unsigned long long kk = sk[tid];
        if (kk != 0ull) {
            mypos = (int)((~(unsigned)kk) & 0x7ffff);
            myval = X[s*NPS + mypos] + alpha * d_g[s*NPS + mypos];
        }
        d_selp[(ka*BATCH + s)*KSEL + tid] = mypos;
        d_selv[(ka*BATCH + s)*KSEL + tid] = myval;
    }
    for (int i = tid; i < IMGPIX; i += 512) syh[i] = 0.f;
    __syncthreads();
    if (mypos >= 0) {
        int a = mypos / SPP, rem = mypos - a*SPP, u = rem / OH, vv = rem - u*OH;
        const float* w = Wg + a*64;
        #pragma unroll
        for (int p = 0; p < 8; p++)
            #pragma unroll
            for (int q = 0; q < 8; q++)
                atomicAdd(&syh[(u+p)*WW + vv + q], myval * w[p*8 + q]);
    }
    __syncthreads();
    float e = 0.f;
    for (int i = tid; i < IMGPIX; i += 512) {
        float d = Y[s*IMGPIX + i] - syh[i];
        e += d*d;
    }
    for (int o = 16; o; o >>= 1) e += __shfl_down_sync(0xffffffffu, e, o);
    if ((tid & 31) == 0) sred[tid >> 5] = e;
    __syncthreads();
    if (tid < 32) {
        e = (tid < 16) ? sred[tid] : 0.f;
        for (int o = 8; o; o >>= 1) e += __shfl_down_sync(0xffffffffu, e, o);
        if (tid == 0) d_errp[ka*BATCH + s] = e;
    }
}

__global__ void k_choose() {
    float l2 = 0.f;
    for (int s = 0; s < BATCH; s++) l2 += d_l2p[s];
    int c = 16;
    for (int k = 0; k < NAL; k++) {
        float e = 0.f;
        for (int s = 0; s < BATCH; s++) e += d_errp[k*BATCH + s];
        if (e < l2) { c = k; break; }
    }
    d_chosen = c;
}

__global__ void k_commit(float* __restrict__ X) {
    int s = blockIdx.x, tid = threadIdx.x;
    int ns = d_nsup[s];
    if (tid < ns) {
        int p = d_supp[s*KSEL + tid];
        if (p >= 0) X[s*NPS + p] = 0.f;
    }
    __syncthreads();
    int c = d_chosen;
    int pos = d_selp[(c*BATCH + s)*KSEL + tid];
    float val = d_selv[(c*BATCH + s)*KSEL + tid];
    if (pos >= 0) X[s*NPS + pos] = val;
    d_supp[s*KSEL + tid] = pos;
    if (tid == 0) d_nsup[s] = KSEL;
}

// ---------------- launch ----------------
extern "C" void kernel_launch(void* const* d_in, const int* in_sizes, int n_in,
                              void* d_out, int out_size) {
    const float* Y  = (const float*)d_in[0];
    const float* Wg = (const float*)d_in[1];
    float* X = (float*)d_out;

    k_init<<<2048, 256>>>(X);
    for (int it = 0; it < 3; it++) {
        k_iter_init<<<512, 256>>>();
        k_residual<<<BATCH, 256>>>(Y, Wg, X);
        k_conv_g<<<256, 256>>>(Wg);
        k_hist<<<dim3(51, BATCH), 256>>>();
        k_thresh<<<BATCH, 256>>>();
        k_collect<<<dim3(51, BATCH), 256>>>();
        k_suppl<<<BATCH, 256>>>();
        k_attempt<<<dim3(NAL, BATCH), 512>>>(Y, Wg, X);
        k_choose<<<1, 1>>>();
        k_commit<<<BATCH, 256>>>(X);
    }
}

// round 2
// speedup vs baseline: 1.3715x; 1.3715x over previous
#include <cuda_runtime.h>

typedef unsigned long long ull;

#define BATCH 32
#define NATOM 128
#define HH 64
#define WW 64
#define OH 57
#define SPP (OH*OH)           // 3249
#define NPS (NATOM*SPP)       // 415872
#define KSEL 256
#define NAL 17
#define CAP 2048
#define NBINS 4096
#define IMGPIX (HH*WW)        // 4096

// ---------------- device state ----------------
__device__ float d_R[BATCH*IMGPIX];
__device__ float d_g[BATCH*NPS];              // ~53 MB
__device__ int   d_hist[BATCH*NBINS];
__device__ int   d_thr[BATCH];
__device__ int   d_ccnt[BATCH];
__device__ int   d_cpos[BATCH*CAP];
__device__ float d_cg[BATCH*CAP];
__device__ float d_cx[BATCH*CAP];
__device__ int   d_selp[NAL*BATCH*KSEL];
__device__ float d_selv[NAL*BATCH*KSEL];
__device__ float d_errp[NAL*BATCH];
__device__ float d_l2p[BATCH];
__device__ int   d_supp[BATCH*KSEL];
__device__ int   d_nsup[BATCH];

// ---------------- kernels ----------------

__global__ void k_init(float* __restrict__ X) {
    int stride = gridDim.x * blockDim.x;
    for (int i = blockIdx.x * blockDim.x + threadIdx.x; i < BATCH*NPS; i += stride)
        X[i] = 0.f;
    if (blockIdx.x == 0 && threadIdx.x < BATCH) d_nsup[threadIdx.x] = 0;
}

// residual R = Y - conv_D(X_sparse); per-sample l2; zero hist/ccnt for this iter
__global__ void k_residual(const float* __restrict__ Y, const float* __restrict__ Wg,
                           const float* __restrict__ X) {
    __shared__ float syh[IMGPIX];
    __shared__ float sred[8];
    int s = blockIdx.x, tid = threadIdx.x;
    for (int i = tid; i < NBINS; i += 256) d_hist[s*NBINS + i] = 0;
    if (tid == 0) d_ccnt[s] = 0;
    for (int i = tid; i < IMGPIX; i += 256) syh[i] = 0.f;
    __syncthreads();
    int ns = d_nsup[s];
    if (tid < ns) {
        int pos = d_supp[s*KSEL + tid];
        if (pos >= 0) {
            float val = X[s*NPS + pos];
            int a = pos / SPP, rem = pos - a*SPP, u = rem / OH, v = rem - u*OH;
            const float* w = Wg + a*64;
            #pragma unroll
            for (int p = 0; p < 8; p++)
                #pragma unroll
                for (int q = 0; q < 8; q++)
                    atomicAdd(&syh[(u+p)*WW + v + q], val * w[p*8 + q]);
        }
    }
    __syncthreads();
    float e = 0.f;
    for (int i = tid; i < IMGPIX; i += 256) {
        float r = Y[s*IMGPIX + i] - syh[i];
        d_R[s*IMGPIX + i] = r;
        e += r*r;
    }
    for (int o = 16; o; o >>= 1) e += __shfl_down_sync(0xffffffffu, e, o);
    if ((tid & 31) == 0) sred[tid >> 5] = e;
    __syncthreads();
    if (tid < 32) {
        e = (tid < 8) ? sred[tid] : 0.f;
        for (int o = 4; o; o >>= 1) e += __shfl_down_sync(0xffffffffu, e, o);
        if (tid == 0) d_l2p[s] = e;
    }
}

// g[b,a,u,v] = sum_{p,q} R[b,u+p,v+q] * W[a,q,p]; fused |g| histogram.
// grid: 32 samples x 8 atom-groups x 4 u-chunks = 1024 blocks, 256 threads.
// FFMA2 (fma.rn.f32x2) pairs accumulators along the atom dimension.
__global__ void __launch_bounds__(256) k_conv_g(const float* __restrict__ Wg) {
    __shared__ float shR[23*64 + 16];
    __shared__ float shW[64*16];      // [p*8+q][a]  (transpose baked in)
    __shared__ int   shH[NBINS];
    int bid = blockIdx.x;
    int s   = bid >> 5;
    int rem = bid & 31;
    int grp = rem >> 2;       // 0..7 : 16 atoms
    int uc  = rem & 3;        // 0..3 : 16 rows of u
    int ub  = uc * 16;
    int abase = grp * 16;
    int tid = threadIdx.x;

    for (int i = tid; i < NBINS; i += 256) shH[i] = 0;
    for (int i = tid; i < 23*64; i += 256) {
        int r = ub + (i >> 6);
        shR[i] = (r < HH) ? d_R[s*IMGPIX + r*WW + (i & 63)] : 0.f;
    }
    if (tid < 16) shR[23*64 + tid] = 0.f;
    for (int i = tid; i < 1024; i += 256) {
        int a = i & 15, pq = i >> 4, p = pq >> 3, q = pq & 7;
        shW[pq*16 + a] = Wg[(abase + a)*64 + q*8 + p];
    }
    __syncthreads();

    int v  = tid & 63;
    int ty = tid >> 6;        // 0..3
    int u0 = ty * 4;          // local row base (within 23-row window)

    ull acc[8][4];
    #pragma unroll
    for (int ap = 0; ap < 8; ap++)
        #pragma unroll
        for (int uu = 0; uu < 4; uu++) acc[ap][uu] = 0ull;

    #pragma unroll 1
    for (int p = 0; p < 8; p++) {
        #pragma unroll
        for (int q = 0; q < 8; q++) {
            ull w2[8];
            const ull* wrow = (const ull*)&shW[(p*8 + q)*16];
            #pragma unroll
            for (int ap = 0; ap < 8; ap++) w2[ap] = wrow[ap];
            #pragma unroll
            for (int uu = 0; uu < 4; uu++) {
                float r = shR[(u0 + uu + p)*64 + v + q];
                ull r2;
                asm("mov.b64 %0, {%1, %1};" : "=l"(r2) : "f"(r));
                #pragma unroll
                for (int ap = 0; ap < 8; ap++)
                    asm("fma.rn.f32x2 %0, %1, %2, %0;"
                        : "+l"(acc[ap][uu]) : "l"(w2[ap]), "l"(r2));
            }
        }
    }

    bool vok = (v < OH);
    #pragma unroll
    for (int uu = 0; uu < 4; uu++) {
        int u = ub + u0 + uu;
        if (vok && u < OH) {
            int base = s*NPS + abase*SPP + u*OH + v;
            #pragma unroll
            for (int ap = 0; ap < 8; ap++) {
                float lo, hi;
                asm("mov.b64 {%0, %1}, %2;" : "=f"(lo), "=f"(hi) : "l"(acc[ap][uu]));
                d_g[base + (2*ap)*SPP]   = lo;
                d_g[base + (2*ap+1)*SPP] = hi;
                atomicAdd(&shH[(__float_as_uint(lo) & 0x7fffffffu) >> 19], 1);
                atomicAdd(&shH[(__float_as_uint(hi) & 0x7fffffffu) >> 19], 1);
            }
        }
    }
    __syncthreads();
    for (int i = tid; i < NBINS; i += 256)
        if (shH[i]) atomicAdd(&d_hist[s*NBINS + i], shH[i]);
}

__global__ void k_thresh() {
    __shared__ int seg[256];
    int s = blockIdx.x, t = threadIdx.x;
    int sum = 0;
    for (int b = t*16; b < t*16 + 16; b++) sum += d_hist[s*NBINS + b];
    seg[t] = sum;
    __syncthreads();
    if (t == 0) {
        int cum = 0, thr = 0;
        for (int j = 255; j >= 0; j--) {
            if (cum + seg[j] >= 2*KSEL) {
                for (int b = j*16 + 15; b >= j*16; b--) {
                    cum += d_hist[s*NBINS + b];
                    if (cum >= 2*KSEL) { thr = b; break; }
                }
                break;
            }
            cum += seg[j];
        }
        d_thr[s] = thr;
    }
}

// chunks 0..50 scan g; chunk 51 appends support entries below threshold.
// captures X value per candidate so k_attempt never touches dense X.
__global__ void k_collect(const float* __restrict__ X) {
    int s = blockIdx.y, chunk = blockIdx.x, tid = threadIdx.x;
    if (chunk == 51) {
        int ns = d_nsup[s];
        if (tid < ns) {
            int pos = d_supp[s*KSEL + tid];
            if (pos >= 0) {
                float gv = d_g[s*NPS + pos];
                int key = (int)((__float_as_uint(gv) & 0x7fffffffu) >> 19);
                if (key < d_thr[s]) {
                    int idx = atomicAdd(&d_ccnt[s], 1);
                    if (idx < CAP) {
                        d_cpos[s*CAP + idx] = pos;
                        d_cg[s*CAP + idx]   = gv;
                        d_cx[s*CAP + idx]   = X[s*NPS + pos];
                    }
                }
            }
        }
        return;
    }
    int thr = d_thr[s];
    int base = chunk * 8192;
    int end = base + 8192; if (end > NPS) end = NPS;
    for (int i = base + tid; i < end; i += 256) {
        float gv = d_g[s*NPS + i];
        int key = (int)((__float_as_uint(gv) & 0x7fffffffu) >> 19);
        if (key >= thr) {
            int idx = atomicAdd(&d_ccnt[s], 1);
            if (idx < CAP) {
                d_cpos[s*CAP + idx] = i;
                d_cg[s*CAP + idx]   = gv;
                d_cx[s*CAP + idx]   = X[s*NPS + i];
            }
        }
    }
}

// one block per (alpha, sample): exact top-256 via radix-select on unique
// 51-bit keys (abs<<19 | ~pos); then sparse reconstruction + err.
__global__ void __launch_bounds__(512) k_attempt(const float* __restrict__ Y,
                                                 const float* __restrict__ Wg) {
    __shared__ ull   skey[CAP];
    __shared__ float sval[CAP];
    __shared__ unsigned aux[NBINS];   // hist, then reused as syh (float bits)
    __shared__ int   ssum[512];
    __shared__ ull   s_prefix, s_T;
    __shared__ int   s_m, s_done, s_cnt;
    __shared__ float sred[16];

    int ka = blockIdx.x, s = blockIdx.y, tid = threadIdx.x;
    float alpha = 1.0f / (float)(1 << ka);
    int n = d_ccnt[s]; if (n > CAP) n = CAP;

    for (int i = tid; i < CAP; i += 512) {
        ull kk = 0ull; float val = 0.f;
        if (i < n) {
            int pos = d_cpos[s*CAP + i];
            val = d_cx[s*CAP + i] + alpha * d_cg[s*CAP + i];
            unsigned ab = __float_as_uint(val) & 0x7fffffffu;
            kk = ((ull)ab << 19) | (unsigned)((~pos) & 0x7ffff);
        }
        skey[i] = kk; sval[i] = val;
    }
    if (tid == 0) { s_prefix = 0ull; s_m = KSEL; s_done = (n <= KSEL) ? 1 : 0; s_T = 1ull; }
    __syncthreads();

    for (int lvl = 0; lvl < 5; lvl++) {
        if (!s_done) {
            int shift = 48 - 12*lvl;
            for (int i = tid; i < NBINS; i += 512) aux[i] = 0u;
            __syncthreads();
            ull pref = s_prefix; int m = s_m;
            ull himask = ~(((ull)1 << (shift + 12)) - 1);
            for (int i = tid; i < n; i += 512) {
                ull k = skey[i];
                if ((k & himask) == pref)
                    atomicAdd(&aux[(unsigned)((k >> shift) & 0xFFF)], 1u);
            }
            __syncthreads();
            int segv = 0;
            #pragma unroll
            for (int j = 0; j < 8; j++) segv += (int)aux[tid*8 + j];
            ssum[tid] = segv;
            __syncthreads();
            for (int off = 1; off < 512; off <<= 1) {
                int add = (tid + off < 512) ? ssum[tid + off] : 0;
                __syncthreads();
                ssum[tid] += add;
                __syncthreads();
            }
            if (ssum[tid] >= m && (tid == 511 || ssum[tid+1] < m)) {
                int cum = (tid == 511) ? 0 : ssum[tid+1];
                int b = tid*8;
                for (int j = 7; j >= 0; j--) {
                    int c = (int)aux[tid*8 + j];
                    cum += c;
                    if (cum >= m) { b = tid*8 + j; break; }
                }
                int h_b = (int)aux[b];
                ull npref = pref | ((ull)b << shift);
                if (cum == m || shift == 0) { s_T = npref; s_done = 1; }
                else { s_prefix = npref; s_m = m - (cum - h_b); }
            }
            __syncthreads();
        }
    }
    __syncthreads();
    ull T = s_T;

    // prepare output slots + syh
    int selbase = (ka*BATCH + s)*KSEL;
    if (tid < KSEL) d_selp[selbase + tid] = -1;
    for (int i = tid; i < IMGPIX; i += 512) aux[i] = 0u;   // 0.0f
    if (tid == 0) s_cnt = 0;
    __syncthreads();

    float* syh = (float*)aux;
    for (int i = tid; i < n; i += 512) {
        ull k = skey[i];
        if (k >= T) {
            int slot = atomicAdd(&s_cnt, 1);
            int pos = (int)((~(unsigned)k) & 0x7ffff);
            float val = sval[i];
            d_selp[selbase + slot] = pos;
            d_selv[selbase + slot] = val;
            int a = pos / SPP, rem = pos - a*SPP, u = rem / OH, vv = rem - u*OH;
            const float* w = Wg + a*64;
            #pragma unroll
            for (int p = 0; p < 8; p++)
                #pragma unroll
                for (int q = 0; q < 8; q++)
                    atomicAdd(&syh[(u+p)*WW + vv + q], val * w[p*8 + q]);
        }
    }
    __syncthreads();
    float e = 0.f;
    for (int i = tid; i < IMGPIX; i += 512) {
        float d = Y[s*IMGPIX + i] - syh[i];
        e += d*d;
    }
    for (int o = 16; o; o >>= 1) e += __shfl_down_sync(0xffffffffu, e, o);
    if ((tid & 31) == 0) sred[tid >> 5] = e;
    __syncthreads();
    if (tid < 32) {
        e = (tid < 16) ? sred[tid] : 0.f;
        for (int o = 8; o; o >>= 1) e += __shfl_down_sync(0xffffffffu, e, o);
        if (tid == 0) d_errp[ka*BATCH + s] = e;
    }
}

// commit: per-block redundant alpha choice, then scatter-update X + support
__global__ void k_commit(float* __restrict__ X) {
    __shared__ int sc;
    int s = blockIdx.x, tid = threadIdx.x;
    if (tid == 0) {
        float l2 = 0.f;
        for (int s2 = 0; s2 < BATCH; s2++) l2 += d_l2p[s2];
        int c = NAL - 1;
        for (int k = 0; k < NAL; k++) {
            float e = 0.f;
            for (int s2 = 0; s2 < BATCH; s2++) e += d_errp[k*BATCH + s2];
            if (e < l2) { c = k; break; }
        }
        sc = c;
    }
    int ns = d_nsup[s];
    if (tid < ns) {
        int p = d_supp[s*KSEL + tid];
        if (p >= 0) X[s*NPS + p] = 0.f;
    }
    __syncthreads();
    int c = sc;
    int pos = d_selp[(c*BATCH + s)*KSEL + tid];
    float val = d_selv[(c*BATCH + s)*KSEL + tid];
    if (pos >= 0) X[s*NPS + pos] = val;
    d_supp[s*KSEL + tid] = pos;
    if (tid == 0) d_nsup[s] = KSEL;
}

// ---------------- launch ----------------
extern "C" void kernel_launch(void* const* d_in, const int* in_sizes, int n_in,
                              void* d_out, int out_size) {
    const float* Y  = (const float*)d_in[0];
    const float* Wg = (const float*)d_in[1];
    float* X = (float*)d_out;

    k_init<<<2048, 256>>>(X);
    for (int it = 0; it < 3; it++) {
        k_residual<<<BATCH, 256>>>(Y, Wg, X);
        k_conv_g<<<1024, 256>>>(Wg);
        k_thresh<<<BATCH, 256>>>();
        k_collect<<<dim3(52, BATCH), 256>>>(X);
        k_attempt<<<dim3(NAL, BATCH), 512>>>(Y, Wg);
        k_commit<<<BATCH, KSEL>>>(X);
    }
}